// round 2
// baseline (speedup 1.0000x reference)
#include <cuda_runtime.h>
#include <cstdint>
#include <math.h>

#define DIM 128
#define NCLUST 512
#define TOPK 8
#define PPART 64
#define NCAND 12
#define COS_EPS 1e-8f
#define NEG_INF (-3.402823466e38f)

// ---------------- scratch (no allocations allowed) ----------------
__device__ float g_dictT[DIM * NCLUST];                 // raw dict transposed [k][c]
__device__ float g_dn[NCLUST];                          // fp32 column norms (fp64-accum, correctly rounded)
__device__ float g_invdn[NCLUST];                       // 1/dn (approx path only)
__device__ float g_csize[PPART * NCLUST];
__device__ float g_isum[(size_t)PPART * NCLUST * DIM];

// ---------------- f32x2 helpers ----------------
__device__ __forceinline__ unsigned long long pk2(float a, float b) {
    unsigned long long r;
    asm("mov.b64 %0, {%1, %2};" : "=l"(r) : "f"(a), "f"(b));
    return r;
}
__device__ __forceinline__ void fma2(unsigned long long& d, unsigned long long a, unsigned long long b) {
    asm("fma.rn.f32x2 %0, %1, %2, %0;" : "+l"(d) : "l"(a), "l"(b));
}
__device__ __forceinline__ void upk2(unsigned long long v, float& a, float& b) {
    asm("mov.b64 {%0, %1}, %2;" : "=f"(a), "=f"(b) : "l"(v));
}

// ---------------- kernel 1: transpose dict + exact-ish column norms ----------------
__global__ void prep_kernel(const float* __restrict__ dict) {
    int c = blockIdx.x;      // 512
    int d = threadIdx.x;     // 128
    __shared__ double red[DIM];
    float v = dict[c * DIM + d];
    red[d] = (double)v * (double)v;
    __syncthreads();
#pragma unroll
    for (int s = 64; s > 0; s >>= 1) {
        if (d < s) red[d] += red[d + s];
        __syncthreads();
    }
    g_dictT[d * NCLUST + c] = v;
    if (d == 0) {
        float dn = fmaxf(sqrtf((float)red[0]), COS_EPS);
        g_dn[c] = dn;
        g_invdn[c] = 1.0f / dn;
    }
}

// ---------------- kernel 2: approximate distances GEMM (fp32 via f32x2) ----------------
__global__ __launch_bounds__(256, 1)
void gemm_dist_kernel(const float* __restrict__ x, float* __restrict__ dist) {
    extern __shared__ float sm[];
    float* As = sm;                 // [128][128] (row, k)
    float* Bs = sm + 128 * 128;     // [128][128] (k, col)
    __shared__ float rinv[128];
    __shared__ float sinv[128];

    const int rowTile = blockIdx.y;
    const int colTile = blockIdx.x;
    const int t = threadIdx.x;
    const int l = t & 31;
    const int w = t >> 5;

    if (t < 128) sinv[t] = g_invdn[colTile * 128 + t];

    const float* xbase = x + (size_t)rowTile * 128 * DIM;
#pragma unroll
    for (int i = 0; i < 16; ++i) {
        int r = w + 8 * i;
        float4 v = *(const float4*)(xbase + r * DIM + l * 4);
        *(float4*)(As + r * 128 + l * 4) = v;
        float sq = v.x * v.x + v.y * v.y + v.z * v.z + v.w * v.w;
#pragma unroll
        for (int o = 16; o; o >>= 1) sq += __shfl_xor_sync(0xffffffffu, sq, o);
        if (l == 0) rinv[r] = 1.0f / fmaxf(sqrtf(sq), COS_EPS);
    }
    const float* bbase = g_dictT + colTile * 128;
#pragma unroll
    for (int i = 0; i < 16; ++i) {
        int k = w + 8 * i;
        *(float4*)(Bs + k * 128 + l * 4) = *(const float4*)(bbase + k * NCLUST + l * 4);
    }
    __syncthreads();

    const int tx = t & 15;
    const int ty = t >> 4;

    unsigned long long acc[8][4];
#pragma unroll
    for (int i = 0; i < 8; ++i)
#pragma unroll
        for (int j = 0; j < 4; ++j) acc[i][j] = 0ULL;

    for (int k0 = 0; k0 < 128; k0 += 4) {
        float4 a[8];
#pragma unroll
        for (int i = 0; i < 8; ++i)
            a[i] = *(const float4*)(As + (ty * 8 + i) * 128 + k0);
#pragma unroll
        for (int kk = 0; kk < 4; ++kk) {
            float4 bl = *(const float4*)(Bs + (k0 + kk) * 128 + tx * 8);
            float4 bh = *(const float4*)(Bs + (k0 + kk) * 128 + tx * 8 + 4);
            unsigned long long bp0 = pk2(bl.x, bl.y);
            unsigned long long bp1 = pk2(bl.z, bl.w);
            unsigned long long bp2 = pk2(bh.x, bh.y);
            unsigned long long bp3 = pk2(bh.z, bh.w);
#pragma unroll
            for (int i = 0; i < 8; ++i) {
                float av = (kk == 0) ? a[i].x : (kk == 1) ? a[i].y : (kk == 2) ? a[i].z : a[i].w;
                unsigned long long ap = pk2(av, av);
                fma2(acc[i][0], ap, bp0);
                fma2(acc[i][1], ap, bp1);
                fma2(acc[i][2], ap, bp2);
                fma2(acc[i][3], ap, bp3);
            }
        }
    }

#pragma unroll
    for (int i = 0; i < 8; ++i) {
        int r = ty * 8 + i;
        float ri = rinv[r];
        float o0, o1, o2, o3, o4, o5, o6, o7;
        upk2(acc[i][0], o0, o1);
        upk2(acc[i][1], o2, o3);
        upk2(acc[i][2], o4, o5);
        upk2(acc[i][3], o6, o7);
        int cb = tx * 8;
        size_t off = (size_t)(rowTile * 128 + r) * NCLUST + colTile * 128 + cb;
        float4 s0 = make_float4(o0 * ri * sinv[cb + 0], o1 * ri * sinv[cb + 1],
                                o2 * ri * sinv[cb + 2], o3 * ri * sinv[cb + 3]);
        float4 s1 = make_float4(o4 * ri * sinv[cb + 4], o5 * ri * sinv[cb + 5],
                                o6 * ri * sinv[cb + 6], o7 * ri * sinv[cb + 7]);
        *(float4*)(dist + off) = s0;
        *(float4*)(dist + off + 4) = s1;
    }
}

// ---------------- kernel 3: candidates + exact re-rank + softmax + outputs ----------------
__device__ __forceinline__ bool better(float av, int ai, float bv, int bi) {
    return (av > bv) || (av == bv && ai < bi);
}
__device__ __forceinline__ void ins12(float (&lv)[NCAND], int (&li)[NCAND], float v, int ix) {
    if (better(v, ix, lv[NCAND - 1], li[NCAND - 1])) {
        lv[NCAND - 1] = v; li[NCAND - 1] = ix;
#pragma unroll
        for (int j = NCAND - 1; j > 0; --j) {
            if (better(lv[j], li[j], lv[j - 1], li[j - 1])) {
                float tv = lv[j]; lv[j] = lv[j - 1]; lv[j - 1] = tv;
                int ti = li[j]; li[j] = li[j - 1]; li[j - 1] = ti;
            }
        }
    }
}
__device__ __forceinline__ void red4(float* ptr, float a, float b, float c, float d) {
    asm volatile("red.global.add.v4.f32 [%0], {%1,%2,%3,%4};"
                 :: "l"(ptr), "f"(a), "f"(b), "f"(c), "f"(d) : "memory");
}

// per-warp smem: 12 padded dict rows (129 floats each) + x row (132 floats)
#define WARP_SM (NCAND * 129 + 132)

__global__ __launch_bounds__(128)
void topk_kernel(const float* __restrict__ dist, const float* __restrict__ x,
                 const float* __restrict__ dict, float* __restrict__ ge,
                 float* __restrict__ idxo) {
    __shared__ float sm[4 * WARP_SM];
    const int t = threadIdx.x;
    const int l = t & 31;
    const int w = t >> 5;
    const size_t row = (size_t)blockIdx.x * 4 + w;
    float* drows = sm + w * WARP_SM;
    float* xrow = drows + NCAND * 129;

    // x row -> smem
    {
        float4 xv4 = *(const float4*)(x + row * DIM + l * 4);
        *(float4*)(xrow + l * 4) = xv4;
    }

    // ---- phase A: approx scan, per-lane sorted top-12 ----
    const float* drow = dist + row * NCLUST;
    float lv[NCAND]; int li[NCAND];
#pragma unroll
    for (int j = 0; j < NCAND; ++j) { lv[j] = NEG_INF; li[j] = 0x7FFFFFFF; }
#pragma unroll
    for (int c = 0; c < 4; ++c) {
        float4 v = *(const float4*)(drow + c * 128 + l * 4);
        int base = c * 128 + l * 4;
        ins12(lv, li, v.x, base + 0);
        ins12(lv, li, v.y, base + 1);
        ins12(lv, li, v.z, base + 2);
        ins12(lv, li, v.w, base + 3);
    }

    // ---- phase B: extract global top-12 candidate indices (broadcast to all lanes) ----
    int cand[NCAND];
#pragma unroll
    for (int r = 0; r < NCAND; ++r) {
        float bv = lv[0]; int bi = li[0];
#pragma unroll
        for (int o = 16; o; o >>= 1) {
            float ov = __shfl_xor_sync(0xffffffffu, bv, o);
            int oi = __shfl_xor_sync(0xffffffffu, bi, o);
            if (ov > bv || (ov == bv && oi < bi)) { bv = ov; bi = oi; }
        }
        cand[r] = bi;
        if (li[0] == bi) {
#pragma unroll
            for (int j = 0; j < NCAND - 1; ++j) { lv[j] = lv[j + 1]; li[j] = li[j + 1]; }
            lv[NCAND - 1] = NEG_INF; li[NCAND - 1] = 0x7FFFFFFF;
        }
    }

    // ---- phase C: load 12 candidate dict rows into padded smem (conflict-free) ----
#pragma unroll
    for (int j = 0; j < NCAND; ++j) {
        const float* dr = dict + (size_t)cand[j] * DIM;
#pragma unroll
        for (int q4 = 0; q4 < 4; ++q4)
            drows[j * 129 + q4 * 32 + l] = dr[q4 * 32 + l];
    }
    __syncwarp();

    // ---- xn: fp64-accumulated row norm (correctly rounded to f32) ----
    double s = 0.0;
#pragma unroll
    for (int q4 = 0; q4 < 4; ++q4) {
        double xv = (double)xrow[q4 * 32 + l];
        s += xv * xv;
    }
#pragma unroll
    for (int o = 16; o; o >>= 1) s += __shfl_xor_sync(0xffffffffu, s, o);
    float xn = fmaxf(sqrtf((float)s), COS_EPS);

    // ---- phase D: exact replica of reference arithmetic for 12 candidates ----
    // serial k-ascending FMA dot (matches cublas / Eigen per-element order),
    // then IEEE divide by rn(xn*dn) — identical op sequence to jnp.
    float q = NEG_INF;
    int qi = 0x7FFFFFFF;
    if (l < NCAND) {
        float p = 0.0f;
        const float* dsm = drows + l * 129;   // bank (l + k) % 32 : conflict-free
#pragma unroll
        for (int k = 0; k < DIM; ++k)
            p = fmaf(xrow[k], dsm[k], p);
        qi = cand[l];
        q = __fdiv_rn(p, __fmul_rn(xn, g_dn[qi]));
    }

    // ---- phase E: extract exact top-8 (value desc, index asc) ----
    float tv[8]; int ti[8];
#pragma unroll
    for (int r = 0; r < 8; ++r) {
        float bv = q; int bi = qi;
#pragma unroll
        for (int o = 16; o; o >>= 1) {
            float ov = __shfl_xor_sync(0xffffffffu, bv, o);
            int oi = __shfl_xor_sync(0xffffffffu, bi, o);
            if (ov > bv || (ov == bv && oi < bi)) { bv = ov; bi = oi; }
        }
        tv[r] = bv; ti[r] = bi;
        if (qi == bi) q = NEG_INF;
    }

    // ---- softmaxes (tv[0] is max) ----
    float m = tv[0];
    float e[8], e2[8], se = 0.f, se2 = 0.f;
#pragma unroll
    for (int k = 0; k < 8; ++k) {
        e[k] = expf(tv[k] - m);            se += e[k];
        e2[k] = expf(20.0f * (tv[k] - m)); se2 += e2[k];
    }
    float wgt[8], ew[8];
#pragma unroll
    for (int k = 0; k < 8; ++k) { wgt[k] = e[k] / se; ew[k] = e2[k] / se2; }

    // ---- group_emb ----
    float4 xv = *(const float4*)(xrow + l * 4);
    float4 g = make_float4(0.f, 0.f, 0.f, 0.f);
#pragma unroll
    for (int k = 0; k < 8; ++k) {
        float4 dv = *(const float4*)(dict + (size_t)ti[k] * DIM + l * 4);
        g.x += wgt[k] * dv.x; g.y += wgt[k] * dv.y;
        g.z += wgt[k] * dv.z; g.w += wgt[k] * dv.w;
    }
    *(float4*)(ge + row * DIM + l * 4) = g;

    if (l == 0) {
        float4 u0 = make_float4((float)ti[0], (float)ti[1], (float)ti[2], (float)ti[3]);
        float4 u1 = make_float4((float)ti[4], (float)ti[5], (float)ti[6], (float)ti[7]);
        *(float4*)(idxo + row * TOPK) = u0;
        *(float4*)(idxo + row * TOPK + 4) = u1;
    }

    // ---- scatter-reduce EMA statistics ----
    const int p = (int)(blockIdx.x & (PPART - 1));
    if (l < 8) {
        int myti = ti[l];
        float myw = ew[l];
        atomicAdd(g_csize + p * NCLUST + myti, myw);
    }
#pragma unroll
    for (int k = 0; k < 8; ++k) {
        float sc = ew[k];
        float* ptr = g_isum + ((size_t)p * NCLUST + (size_t)ti[k]) * DIM + l * 4;
        red4(ptr, sc * xv.x, sc * xv.y, sc * xv.z, sc * xv.w);
    }
}

// ---------------- kernel 4: finalize EMA dictionary ----------------
__global__ void finalize_kernel(const float* __restrict__ dict, float* __restrict__ ndict) {
    int c = blockIdx.x;
    int d = threadIdx.x;
    float cs = 0.f;
#pragma unroll 8
    for (int p = 0; p < PPART; ++p) cs += g_csize[p * NCLUST + c];
    float s = 0.f;
#pragma unroll 8
    for (int p = 0; p < PPART; ++p) s += g_isum[((size_t)p * NCLUST + c) * DIM + d];
    float dv = dict[c * DIM + d];
    float nv = (cs != 0.0f) ? (dv * 0.1f + (s / cs) * 0.9f) : dv;
    ndict[c * DIM + d] = nv;
}

// ---------------- launch ----------------
extern "C" void kernel_launch(void* const* d_in, const int* in_sizes, int n_in,
                              void* d_out, int out_size) {
    const float* x = (const float*)d_in[0];
    const float* dict = (const float*)d_in[1];
    const size_t N = (size_t)in_sizes[0] / DIM;

    float* out = (float*)d_out;
    float* ge    = out;
    float* idxo  = ge + N * DIM;
    float* dist  = idxo + N * TOPK;
    float* ndict = dist + N * NCLUST;

    void* pcs = nullptr; void* pis = nullptr;
    cudaGetSymbolAddress(&pcs, g_csize);
    cudaGetSymbolAddress(&pis, g_isum);
    cudaMemsetAsync(pcs, 0, sizeof(float) * PPART * NCLUST);
    cudaMemsetAsync(pis, 0, sizeof(float) * (size_t)PPART * NCLUST * DIM);

    prep_kernel<<<NCLUST, DIM>>>(dict);

    cudaFuncSetAttribute(gemm_dist_kernel,
                         cudaFuncAttributeMaxDynamicSharedMemorySize, 131072);
    dim3 grid(NCLUST / 128, (unsigned)(N / 128));
    gemm_dist_kernel<<<grid, 256, 131072>>>(x, dist);

    topk_kernel<<<(unsigned)(N / 4), 128>>>(dist, x, dict, ge, idxo);

    finalize_kernel<<<NCLUST, DIM>>>(dict, ndict);
}

// round 3
// speedup vs baseline: 1.4171x; 1.4171x over previous
#include <cuda_runtime.h>
#include <cuda_bf16.h>
#include <cstdint>
#include <math.h>

#define DIM 128
#define NCLUST 512
#define TOPK 8
#define PPART 64
#define NCAND 12
#define NMAX 262144
#define COS_EPS 1e-8f
#define NEG_INF (-3.402823466e38f)

#define BM 256
#define BN 128
#define SSTR 136   // smem row stride in halves (conflict-free fragment loads)

// ---------------- scratch ----------------
__device__ __nv_bfloat16 g_dhi[NCLUST * DIM];
__device__ __nv_bfloat16 g_dlo[NCLUST * DIM];
__device__ float g_dn[NCLUST];
__device__ float g_invdn[NCLUST];
__device__ float g_xinv[NMAX];
__device__ float g_csize[PPART * NCLUST];
__device__ float g_isum[(size_t)PPART * NCLUST * DIM];

// ---------------- kernel 0: x row inverse norms ----------------
__global__ __launch_bounds__(256)
void xnorm_kernel(const float* __restrict__ x) {
    const int l = threadIdx.x & 31;
    const int w = threadIdx.x >> 5;
    const size_t row = (size_t)blockIdx.x * 8 + w;
    float4 v = *(const float4*)(x + row * DIM + l * 4);
    float sq = v.x * v.x + v.y * v.y + v.z * v.z + v.w * v.w;
#pragma unroll
    for (int o = 16; o; o >>= 1) sq += __shfl_xor_sync(0xffffffffu, sq, o);
    if (l == 0) g_xinv[row] = 1.0f / fmaxf(sqrtf(sq), COS_EPS);
}

// ---------------- kernel 1: dict split hi/lo + exact norms ----------------
__global__ void prep_kernel(const float* __restrict__ dict) {
    int c = blockIdx.x;
    int d = threadIdx.x;
    __shared__ double red[DIM];
    float v = dict[c * DIM + d];
    red[d] = (double)v * (double)v;
    __syncthreads();
#pragma unroll
    for (int s = 64; s > 0; s >>= 1) {
        if (d < s) red[d] += red[d + s];
        __syncthreads();
    }
    __nv_bfloat16 hi = __float2bfloat16(v);
    float lof = v - __bfloat162float(hi);
    g_dhi[c * DIM + d] = hi;
    g_dlo[c * DIM + d] = __float2bfloat16(lof);
    if (d == 0) {
        float dn = fmaxf(sqrtf((float)red[0]), COS_EPS);
        g_dn[c] = dn;
        g_invdn[c] = 1.0f / dn;
    }
}

// ---------------- mma helper ----------------
__device__ __forceinline__ void mma16816(float* d, uint32_t a0, uint32_t a1, uint32_t a2, uint32_t a3,
                                         uint32_t b0, uint32_t b1) {
    asm volatile("mma.sync.aligned.m16n8k16.row.col.f32.bf16.bf16.f32 "
                 "{%0,%1,%2,%3},{%4,%5,%6,%7},{%8,%9},{%0,%1,%2,%3};"
                 : "+f"(d[0]), "+f"(d[1]), "+f"(d[2]), "+f"(d[3])
                 : "r"(a0), "r"(a1), "r"(a2), "r"(a3), "r"(b0), "r"(b1));
}

// ---------------- kernel 2: distances GEMM (bf16x3 tensor cores) ----------------
__global__ __launch_bounds__(256, 1)
void gemm_bf16x3(const float* __restrict__ x, float* __restrict__ dist) {
    extern __shared__ __nv_bfloat16 smh[];
    __nv_bfloat16* Ahi = smh;
    __nv_bfloat16* Alo = Ahi + BM * SSTR;
    __nv_bfloat16* Bhi = Alo + BM * SSTR;
    __nv_bfloat16* Blo = Bhi + BN * SSTR;
    __shared__ float srinv[BM];
    __shared__ float ssinv[BN];

    const int t = threadIdx.x;
    const int l = t & 31;
    const int wid = t >> 5;
    const int rowBase = blockIdx.y * BM;
    const int colBase = blockIdx.x * BN;

    if (t < BN) ssinv[t] = g_invdn[colBase + t];
    srinv[t] = g_xinv[rowBase + t];

    // A tile: 256 rows x 128 floats -> split hi/lo bf16
    const float4* xb = (const float4*)(x + (size_t)rowBase * DIM);
#pragma unroll
    for (int i = 0; i < 32; ++i) {
        int flat = i * 256 + t;
        int r = flat >> 5, c4 = flat & 31;
        float4 v = xb[flat];
        __nv_bfloat162 h01 = __floats2bfloat162_rn(v.x, v.y);
        __nv_bfloat162 h23 = __floats2bfloat162_rn(v.z, v.w);
        __nv_bfloat162 l01 = __floats2bfloat162_rn(v.x - __bfloat162float(h01.x),
                                                   v.y - __bfloat162float(h01.y));
        __nv_bfloat162 l23 = __floats2bfloat162_rn(v.z - __bfloat162float(h23.x),
                                                   v.w - __bfloat162float(h23.y));
        __nv_bfloat16* ah = Ahi + r * SSTR + c4 * 4;
        __nv_bfloat16* al = Alo + r * SSTR + c4 * 4;
        *(__nv_bfloat162*)(ah) = h01;
        *(__nv_bfloat162*)(ah + 2) = h23;
        *(__nv_bfloat162*)(al) = l01;
        *(__nv_bfloat162*)(al + 2) = l23;
    }
    // B tile: 128 dict rows x 128 halves (hi and lo)
    {
        const uint4* bh = (const uint4*)(g_dhi + (size_t)colBase * DIM);
        const uint4* bl = (const uint4*)(g_dlo + (size_t)colBase * DIM);
#pragma unroll
        for (int i = 0; i < 8; ++i) {
            int flat = i * 256 + t;
            int r = flat >> 4, h8 = flat & 15;
            *(uint4*)(Bhi + r * SSTR + h8 * 8) = bh[flat];
            *(uint4*)(Blo + r * SSTR + h8 * 8) = bl[flat];
        }
    }
    __syncthreads();

    const int wm = (wid >> 1) * 64;
    const int wn = (wid & 1) * 64;
    const int g = l >> 2;
    const int tg = l & 3;

    float acc[4][8][4];
#pragma unroll
    for (int m = 0; m < 4; ++m)
#pragma unroll
        for (int n = 0; n < 8; ++n)
#pragma unroll
            for (int j = 0; j < 4; ++j) acc[m][n][j] = 0.0f;

#pragma unroll
    for (int ks = 0; ks < 8; ++ks) {
        const int k = ks * 16 + 2 * tg;
        uint32_t bh0[8], bh1[8], bl0[8], bl1[8];
#pragma unroll
        for (int n = 0; n < 8; ++n) {
            int col = wn + n * 8 + g;
            const __nv_bfloat16* bp = Bhi + col * SSTR + k;
            bh0[n] = *(const uint32_t*)(bp);
            bh1[n] = *(const uint32_t*)(bp + 8);
            const __nv_bfloat16* bq = Blo + col * SSTR + k;
            bl0[n] = *(const uint32_t*)(bq);
            bl1[n] = *(const uint32_t*)(bq + 8);
        }
#pragma unroll
        for (int m = 0; m < 4; ++m) {
            int row = wm + m * 16 + g;
            const __nv_bfloat16* ap = Ahi + row * SSTR + k;
            uint32_t a0 = *(const uint32_t*)(ap);
            uint32_t a1 = *(const uint32_t*)(ap + 8 * SSTR);
            uint32_t a2 = *(const uint32_t*)(ap + 8);
            uint32_t a3 = *(const uint32_t*)(ap + 8 * SSTR + 8);
            const __nv_bfloat16* aq = Alo + row * SSTR + k;
            uint32_t e0 = *(const uint32_t*)(aq);
            uint32_t e1 = *(const uint32_t*)(aq + 8 * SSTR);
            uint32_t e2 = *(const uint32_t*)(aq + 8);
            uint32_t e3 = *(const uint32_t*)(aq + 8 * SSTR + 8);
#pragma unroll
            for (int n = 0; n < 8; ++n) {
                mma16816(acc[m][n], a0, a1, a2, a3, bh0[n], bh1[n]);
                mma16816(acc[m][n], a0, a1, a2, a3, bl0[n], bl1[n]);
                mma16816(acc[m][n], e0, e1, e2, e3, bh0[n], bh1[n]);
            }
        }
    }

    // epilogue: dist = p * (1/xn) * (1/dn)
#pragma unroll
    for (int m = 0; m < 4; ++m) {
#pragma unroll
        for (int n = 0; n < 8; ++n) {
            int r0 = wm + m * 16 + g;
            int c0 = wn + n * 8 + 2 * tg;
            float ri0 = srinv[r0], ri1 = srinv[r0 + 8];
            float s0 = ssinv[c0], s1 = ssinv[c0 + 1];
            size_t base0 = (size_t)(rowBase + r0) * NCLUST + colBase + c0;
            float2 o0 = make_float2(acc[m][n][0] * ri0 * s0, acc[m][n][1] * ri0 * s1);
            float2 o1 = make_float2(acc[m][n][2] * ri1 * s0, acc[m][n][3] * ri1 * s1);
            *(float2*)(dist + base0) = o0;
            *(float2*)(dist + base0 + 8 * NCLUST) = o1;
        }
    }
}

// ---------------- kernel 3: candidates + exact re-rank + outputs ----------------
__device__ __forceinline__ bool better(float av, int ai, float bv, int bi) {
    return (av > bv) || (av == bv && ai < bi);
}
__device__ __forceinline__ void ins12(float (&lv)[NCAND], int (&li)[NCAND], float v, int ix) {
    if (better(v, ix, lv[NCAND - 1], li[NCAND - 1])) {
        lv[NCAND - 1] = v; li[NCAND - 1] = ix;
#pragma unroll
        for (int j = NCAND - 1; j > 0; --j) {
            if (better(lv[j], li[j], lv[j - 1], li[j - 1])) {
                float tv = lv[j]; lv[j] = lv[j - 1]; lv[j - 1] = tv;
                int ti = li[j]; li[j] = li[j - 1]; li[j - 1] = ti;
            }
        }
    }
}
__device__ __forceinline__ void red4(float* ptr, float a, float b, float c, float d) {
    asm volatile("red.global.add.v4.f32 [%0], {%1,%2,%3,%4};"
                 :: "l"(ptr), "f"(a), "f"(b), "f"(c), "f"(d) : "memory");
}

#define DSTR 132
#define WARP_SM (NCAND * DSTR + DSTR)

__global__ __launch_bounds__(128)
void topk_kernel(const float* __restrict__ dist, const float* __restrict__ x,
                 const float* __restrict__ dict, float* __restrict__ ge,
                 float* __restrict__ idxo) {
    __shared__ float sm[4 * WARP_SM];
    const int t = threadIdx.x;
    const int l = t & 31;
    const int w = t >> 5;
    const size_t row = (size_t)blockIdx.x * 4 + w;
    float* drows = sm + w * WARP_SM;
    float* xrow = drows + NCAND * DSTR;

    {
        float4 xv4 = *(const float4*)(x + row * DIM + l * 4);
        *(float4*)(xrow + l * 4) = xv4;
    }

    // ---- phase A: approx scan, per-lane sorted top-12 ----
    const float* drow = dist + row * NCLUST;
    float lv[NCAND]; int li[NCAND];
#pragma unroll
    for (int j = 0; j < NCAND; ++j) { lv[j] = NEG_INF; li[j] = 0x7FFFFFFF; }
#pragma unroll
    for (int c = 0; c < 4; ++c) {
        float4 v = *(const float4*)(drow + c * 128 + l * 4);
        int base = c * 128 + l * 4;
        ins12(lv, li, v.x, base + 0);
        ins12(lv, li, v.y, base + 1);
        ins12(lv, li, v.z, base + 2);
        ins12(lv, li, v.w, base + 3);
    }

    // ---- phase B: global top-12 candidates ----
    int cand[NCAND];
#pragma unroll
    for (int r = 0; r < NCAND; ++r) {
        float bv = lv[0]; int bi = li[0];
#pragma unroll
        for (int o = 16; o; o >>= 1) {
            float ov = __shfl_xor_sync(0xffffffffu, bv, o);
            int oi = __shfl_xor_sync(0xffffffffu, bi, o);
            if (ov > bv || (ov == bv && oi < bi)) { bv = ov; bi = oi; }
        }
        cand[r] = bi;
        if (li[0] == bi) {
#pragma unroll
            for (int j = 0; j < NCAND - 1; ++j) { lv[j] = lv[j + 1]; li[j] = li[j + 1]; }
            lv[NCAND - 1] = NEG_INF; li[NCAND - 1] = 0x7FFFFFFF;
        }
    }

    // ---- phase C: candidate dict rows -> smem ----
#pragma unroll
    for (int j = 0; j < NCAND; ++j) {
        const float* dr = dict + (size_t)cand[j] * DIM;
#pragma unroll
        for (int q4 = 0; q4 < 4; ++q4)
            drows[j * DSTR + q4 * 32 + l] = dr[q4 * 32 + l];
    }
    __syncwarp();

    // ---- exact x norm (fp64 accumulate) ----
    double s = 0.0;
#pragma unroll
    for (int q4 = 0; q4 < 4; ++q4) {
        double xv = (double)xrow[q4 * 32 + l];
        s += xv * xv;
    }
#pragma unroll
    for (int o = 16; o; o >>= 1) s += __shfl_xor_sync(0xffffffffu, s, o);
    float xn = fmaxf(sqrtf((float)s), COS_EPS);

    // ---- phase D: exact fp32 serial-FMA dot + IEEE divide ----
    float q = NEG_INF;
    int qi = 0x7FFFFFFF;
    int qs = l;
    if (l < NCAND) {
        float p = 0.0f;
        const float* dsm = drows + l * DSTR;
#pragma unroll
        for (int k = 0; k < DIM; ++k)
            p = fmaf(xrow[k], dsm[k], p);
        qi = cand[l];
        q = __fdiv_rn(p, __fmul_rn(xn, g_dn[qi]));
    }

    // ---- phase E: exact top-8 (value desc, index asc), carry slot ----
    float tv[8]; int ti[8]; int ts[8];
#pragma unroll
    for (int r = 0; r < 8; ++r) {
        float bv = q; int bi = qi; int bs = qs;
#pragma unroll
        for (int o = 16; o; o >>= 1) {
            float ov = __shfl_xor_sync(0xffffffffu, bv, o);
            int oi = __shfl_xor_sync(0xffffffffu, bi, o);
            int os = __shfl_xor_sync(0xffffffffu, bs, o);
            if (ov > bv || (ov == bv && oi < bi)) { bv = ov; bi = oi; bs = os; }
        }
        tv[r] = bv; ti[r] = bi; ts[r] = bs;
        if (qi == bi) q = NEG_INF;
    }

    // ---- softmaxes ----
    float m = tv[0];
    float e[8], e2[8], se = 0.f, se2 = 0.f;
#pragma unroll
    for (int k = 0; k < 8; ++k) {
        e[k] = expf(tv[k] - m);            se += e[k];
        e2[k] = expf(20.0f * (tv[k] - m)); se2 += e2[k];
    }
    float wgt[8], ew[8];
#pragma unroll
    for (int k = 0; k < 8; ++k) { wgt[k] = e[k] / se; ew[k] = e2[k] / se2; }

    // ---- group_emb from smem candidate rows ----
    float4 xv = *(const float4*)(xrow + l * 4);
    float4 g = make_float4(0.f, 0.f, 0.f, 0.f);
#pragma unroll
    for (int k = 0; k < 8; ++k) {
        float4 dv = *(const float4*)(drows + ts[k] * DSTR + l * 4);
        g.x += wgt[k] * dv.x; g.y += wgt[k] * dv.y;
        g.z += wgt[k] * dv.z; g.w += wgt[k] * dv.w;
    }
    *(float4*)(ge + row * DIM + l * 4) = g;

    if (l == 0) {
        float4 u0 = make_float4((float)ti[0], (float)ti[1], (float)ti[2], (float)ti[3]);
        float4 u1 = make_float4((float)ti[4], (float)ti[5], (float)ti[6], (float)ti[7]);
        *(float4*)(idxo + row * TOPK) = u0;
        *(float4*)(idxo + row * TOPK + 4) = u1;
    }

    // ---- scatter-reduce EMA statistics ----
    const int p = (int)(blockIdx.x & (PPART - 1));
    if (l < 8) atomicAdd(g_csize + p * NCLUST + ti[l], ew[l]);
#pragma unroll
    for (int k = 0; k < 8; ++k) {
        float sc = ew[k];
        float* ptr = g_isum + ((size_t)p * NCLUST + (size_t)ti[k]) * DIM + l * 4;
        red4(ptr, sc * xv.x, sc * xv.y, sc * xv.z, sc * xv.w);
    }
}

// ---------------- kernel 4: finalize EMA dictionary ----------------
__global__ void finalize_kernel(const float* __restrict__ dict, float* __restrict__ ndict) {
    int c = blockIdx.x;
    int d = threadIdx.x;
    float cs = 0.f;
#pragma unroll 8
    for (int p = 0; p < PPART; ++p) cs += g_csize[p * NCLUST + c];
    float s = 0.f;
#pragma unroll 8
    for (int p = 0; p < PPART; ++p) s += g_isum[((size_t)p * NCLUST + c) * DIM + d];
    float dv = dict[c * DIM + d];
    float nv = (cs != 0.0f) ? (dv * 0.1f + (s / cs) * 0.9f) : dv;
    ndict[c * DIM + d] = nv;
}

// ---------------- launch ----------------
extern "C" void kernel_launch(void* const* d_in, const int* in_sizes, int n_in,
                              void* d_out, int out_size) {
    const float* x = (const float*)d_in[0];
    const float* dict = (const float*)d_in[1];
    const size_t N = (size_t)in_sizes[0] / DIM;

    float* out = (float*)d_out;
    float* ge    = out;
    float* idxo  = ge + N * DIM;
    float* dist  = idxo + N * TOPK;
    float* ndict = dist + N * NCLUST;

    void* pcs = nullptr; void* pis = nullptr;
    cudaGetSymbolAddress(&pcs, g_csize);
    cudaGetSymbolAddress(&pis, g_isum);
    cudaMemsetAsync(pcs, 0, sizeof(float) * PPART * NCLUST);
    cudaMemsetAsync(pis, 0, sizeof(float) * (size_t)PPART * NCLUST * DIM);

    xnorm_kernel<<<(unsigned)(N / 8), 256>>>(x);
    prep_kernel<<<NCLUST, DIM>>>(dict);

    const int smem = (2 * BM + 2 * BN) * SSTR * (int)sizeof(__nv_bfloat16);
    cudaFuncSetAttribute(gemm_bf16x3, cudaFuncAttributeMaxDynamicSharedMemorySize, smem);
    dim3 grid(NCLUST / BN, (unsigned)(N / BM));
    gemm_bf16x3<<<grid, 256, smem>>>(x, dist);

    topk_kernel<<<(unsigned)(N / 4), 128>>>(dist, x, dict, ge, idxo);

    finalize_kernel<<<NCLUST, DIM>>>(dict, ndict);
}

// round 4
// speedup vs baseline: 1.6552x; 1.1679x over previous
#include <cuda_runtime.h>
#include <cuda_bf16.h>
#include <cstdint>
#include <math.h>

#define DIM 128
#define NCLUST 512
#define TOPK 8
#define PPART 64
#define NCAND 12
#define LDEPTH 8
#define NMAX 262144
#define COS_EPS 1e-8f
#define NEG_INF (-3.402823466e38f)

#define BM 256
#define BN 128
#define SSTR 136   // smem row stride in bf16 halves (conflict-free for ldmatrix)

// ---------------- scratch ----------------
__device__ __nv_bfloat16 g_dhi[NCLUST * DIM];
__device__ __nv_bfloat16 g_dlo[NCLUST * DIM];
__device__ float g_dn[NCLUST];
__device__ float g_invdn[NCLUST];
__device__ float g_xinv[NMAX];
__device__ float g_csize[PPART * NCLUST];
__device__ float g_isum[(size_t)PPART * NCLUST * DIM];

// ---------------- kernel: x row inverse norms ----------------
__global__ __launch_bounds__(256)
void xnorm_kernel(const float* __restrict__ x) {
    const int l = threadIdx.x & 31;
    const int w = threadIdx.x >> 5;
    const size_t row = (size_t)blockIdx.x * 8 + w;
    float4 v = *(const float4*)(x + row * DIM + l * 4);
    float sq = v.x * v.x + v.y * v.y + v.z * v.z + v.w * v.w;
#pragma unroll
    for (int o = 16; o; o >>= 1) sq += __shfl_xor_sync(0xffffffffu, sq, o);
    if (l == 0) g_xinv[row] = 1.0f / fmaxf(sqrtf(sq), COS_EPS);
}

// ---------------- kernel: exact dict norms ----------------
__global__ void prep_norm(const float* __restrict__ dict) {
    int c = blockIdx.x;
    int d = threadIdx.x;
    __shared__ double red[DIM];
    float v = dict[c * DIM + d];
    red[d] = (double)v * (double)v;
    __syncthreads();
#pragma unroll
    for (int s = 64; s > 0; s >>= 1) {
        if (d < s) red[d] += red[d + s];
        __syncthreads();
    }
    if (d == 0) {
        float dn = fmaxf(sqrtf((float)red[0]), COS_EPS);
        g_dn[c] = dn;
        g_invdn[c] = 1.0f / dn;
    }
}

// ---------------- kernel: dict hi/lo split ----------------
__global__ void prep_split(const float* __restrict__ dict) {
    int i = blockIdx.x * 256 + threadIdx.x;
    float v = dict[i];
    __nv_bfloat16 hi = __float2bfloat16(v);
    g_dhi[i] = hi;
    g_dlo[i] = __float2bfloat16(v - __bfloat162float(hi));
}

// ---------------- mma / ldmatrix helpers ----------------
__device__ __forceinline__ void mma16816(float* d, uint32_t a0, uint32_t a1, uint32_t a2, uint32_t a3,
                                         uint32_t b0, uint32_t b1) {
    asm volatile("mma.sync.aligned.m16n8k16.row.col.f32.bf16.bf16.f32 "
                 "{%0,%1,%2,%3},{%4,%5,%6,%7},{%8,%9},{%0,%1,%2,%3};"
                 : "+f"(d[0]), "+f"(d[1]), "+f"(d[2]), "+f"(d[3])
                 : "r"(a0), "r"(a1), "r"(a2), "r"(a3), "r"(b0), "r"(b1));
}
__device__ __forceinline__ void ldmx4(uint32_t* r, const __nv_bfloat16* p) {
    uint32_t a = (uint32_t)__cvta_generic_to_shared(p);
    asm volatile("ldmatrix.sync.aligned.m8n8.x4.shared.b16 {%0,%1,%2,%3}, [%4];"
                 : "=r"(r[0]), "=r"(r[1]), "=r"(r[2]), "=r"(r[3]) : "r"(a));
}

// ---------------- kernel: distances GEMM (bf16x3 tensor cores) ----------------
__global__ __launch_bounds__(256, 1)
void gemm_bf16x3(const float* __restrict__ x, float* __restrict__ dist) {
    extern __shared__ __nv_bfloat16 smh[];
    __nv_bfloat16* Ahi = smh;
    __nv_bfloat16* Alo = Ahi + BM * SSTR;
    __nv_bfloat16* Bhi = Alo + BM * SSTR;
    __nv_bfloat16* Blo = Bhi + BN * SSTR;
    __shared__ float srinv[BM];
    __shared__ float ssinv[BN];

    const int t = threadIdx.x;
    const int l = t & 31;
    const int wid = t >> 5;
    const int rowBase = blockIdx.y * BM;
    const int colBase = blockIdx.x * BN;

    if (t < BN) ssinv[t] = g_invdn[colBase + t];
    srinv[t] = g_xinv[rowBase + t];

    // A tile: 256 rows x 128 floats -> hi/lo bf16
    const float4* xb = (const float4*)(x + (size_t)rowBase * DIM);
#pragma unroll
    for (int i = 0; i < 32; ++i) {
        int flat = i * 256 + t;
        int r = flat >> 5, c4 = flat & 31;
        float4 v = xb[flat];
        __nv_bfloat162 h01 = __floats2bfloat162_rn(v.x, v.y);
        __nv_bfloat162 h23 = __floats2bfloat162_rn(v.z, v.w);
        __nv_bfloat162 l01 = __floats2bfloat162_rn(v.x - __bfloat162float(h01.x),
                                                   v.y - __bfloat162float(h01.y));
        __nv_bfloat162 l23 = __floats2bfloat162_rn(v.z - __bfloat162float(h23.x),
                                                   v.w - __bfloat162float(h23.y));
        __nv_bfloat16* ah = Ahi + r * SSTR + c4 * 4;
        __nv_bfloat16* al = Alo + r * SSTR + c4 * 4;
        *(__nv_bfloat162*)(ah) = h01;
        *(__nv_bfloat162*)(ah + 2) = h23;
        *(__nv_bfloat162*)(al) = l01;
        *(__nv_bfloat162*)(al + 2) = l23;
    }
    // B tile
    {
        const uint4* bh = (const uint4*)(g_dhi + (size_t)colBase * DIM);
        const uint4* bl = (const uint4*)(g_dlo + (size_t)colBase * DIM);
#pragma unroll
        for (int i = 0; i < 8; ++i) {
            int flat = i * 256 + t;
            int r = flat >> 4, h8 = flat & 15;
            *(uint4*)(Bhi + r * SSTR + h8 * 8) = bh[flat];
            *(uint4*)(Blo + r * SSTR + h8 * 8) = bl[flat];
        }
    }
    __syncthreads();

    const int wm = (wid >> 1) * 64;
    const int wn = (wid & 1) * 64;
    const int g = l >> 2;
    const int tg = l & 3;
    const int lrow = l & 15;
    const int lk8 = l >> 4;

    float acc[4][8][4];
#pragma unroll
    for (int m = 0; m < 4; ++m)
#pragma unroll
        for (int n = 0; n < 8; ++n)
#pragma unroll
            for (int j = 0; j < 4; ++j) acc[m][n][j] = 0.0f;

#pragma unroll
    for (int ks = 0; ks < 8; ++ks) {
        const int k = ks * 16;
        uint32_t ah[4][4], al[4][4];
#pragma unroll
        for (int m = 0; m < 4; ++m) {
            int off = (wm + m * 16 + lrow) * SSTR + k + lk8 * 8;
            ldmx4(ah[m], Ahi + off);
            ldmx4(al[m], Alo + off);
        }
#pragma unroll
        for (int nt = 0; nt < 4; ++nt) {
            uint32_t bh[4], bl[4];
            int off = (wn + nt * 16 + lrow) * SSTR + k + lk8 * 8;
            ldmx4(bh, Bhi + off);
            ldmx4(bl, Blo + off);
#pragma unroll
            for (int m = 0; m < 4; ++m) {
#pragma unroll
                for (int s = 0; s < 2; ++s) {
                    int n = nt * 2 + s;
                    mma16816(acc[m][n], ah[m][0], ah[m][1], ah[m][2], ah[m][3], bh[s], bh[s + 2]);
                    mma16816(acc[m][n], ah[m][0], ah[m][1], ah[m][2], ah[m][3], bl[s], bl[s + 2]);
                    mma16816(acc[m][n], al[m][0], al[m][1], al[m][2], al[m][3], bh[s], bh[s + 2]);
                }
            }
        }
    }

    // epilogue
#pragma unroll
    for (int m = 0; m < 4; ++m) {
#pragma unroll
        for (int n = 0; n < 8; ++n) {
            int r0 = wm + m * 16 + g;
            int c0 = wn + n * 8 + 2 * tg;
            float ri0 = srinv[r0], ri1 = srinv[r0 + 8];
            float s0 = ssinv[c0], s1 = ssinv[c0 + 1];
            size_t base0 = (size_t)(rowBase + r0) * NCLUST + colBase + c0;
            float2 o0 = make_float2(acc[m][n][0] * ri0 * s0, acc[m][n][1] * ri0 * s1);
            float2 o1 = make_float2(acc[m][n][2] * ri1 * s0, acc[m][n][3] * ri1 * s1);
            *(float2*)(dist + base0) = o0;
            *(float2*)(dist + base0 + 8 * NCLUST) = o1;
        }
    }
}

// ---------------- topk: u64 key helpers ----------------
__device__ __forceinline__ uint64_t packkey(float v, uint32_t low) {
    uint32_t u = __float_as_uint(v);
    u ^= ((uint32_t)((int)u >> 31)) | 0x80000000u;
    return ((uint64_t)u << 32) | low;
}
__device__ __forceinline__ float unpackval(uint64_t k) {
    uint32_t o = (uint32_t)(k >> 32);
    uint32_t u = (o & 0x80000000u) ? (o & 0x7FFFFFFFu) : ~o;
    return __uint_as_float(u);
}
__device__ __forceinline__ void ins8(uint64_t (&ks)[LDEPTH], uint64_t key) {
    if (key > ks[LDEPTH - 1]) {
        ks[LDEPTH - 1] = key;
#pragma unroll
        for (int j = LDEPTH - 1; j > 0; --j) {
            if (ks[j] > ks[j - 1]) { uint64_t tt = ks[j]; ks[j] = ks[j - 1]; ks[j - 1] = tt; }
        }
    }
}
__device__ __forceinline__ uint64_t warpmax64(uint64_t v) {
#pragma unroll
    for (int o = 16; o; o >>= 1) {
        uint64_t ov = __shfl_xor_sync(0xffffffffu, v, o);
        if (ov > v) v = ov;
    }
    return v;
}
__device__ __forceinline__ void red4(float* ptr, float a, float b, float c, float d) {
    asm volatile("red.global.add.v4.f32 [%0], {%1,%2,%3,%4};"
                 :: "l"(ptr), "f"(a), "f"(b), "f"(c), "f"(d) : "memory");
}

#define DSTR 132
#define WARP_SM (NCAND * DSTR + DSTR)

__global__ __launch_bounds__(128)
void topk_kernel(const float* __restrict__ dist, const float* __restrict__ x,
                 const float* __restrict__ dict, float* __restrict__ ge,
                 float* __restrict__ idxo) {
    __shared__ float sm[4 * WARP_SM];
    const int t = threadIdx.x;
    const int l = t & 31;
    const int w = t >> 5;
    const size_t row = (size_t)blockIdx.x * 4 + w;
    float* drows = sm + w * WARP_SM;
    float* xrow = drows + NCAND * DSTR;

    {
        float4 xv4 = *(const float4*)(x + row * DIM + l * 4);
        *(float4*)(xrow + l * 4) = xv4;
    }

    // ---- phase A: approx scan, per-lane sorted top-8 (u64 keys) ----
    const float* drow = dist + row * NCLUST;
    uint64_t ks[LDEPTH];
#pragma unroll
    for (int j = 0; j < LDEPTH; ++j) ks[j] = 0ULL;
#pragma unroll
    for (int c = 0; c < 4; ++c) {
        float4 v = *(const float4*)(drow + c * 128 + l * 4);
        uint32_t base = 511u - (uint32_t)(c * 128 + l * 4);
        ins8(ks, packkey(v.x, base));
        ins8(ks, packkey(v.y, base - 1));
        ins8(ks, packkey(v.z, base - 2));
        ins8(ks, packkey(v.w, base - 3));
    }

    // ---- phase B: global top-12 candidate indices ----
    int cand[NCAND];
#pragma unroll
    for (int r = 0; r < NCAND; ++r) {
        uint64_t m = warpmax64(ks[0]);
        cand[r] = 511 - (int)((uint32_t)m & 0x1FFu);
        if (ks[0] == m) {
#pragma unroll
            for (int j = 0; j < LDEPTH - 1; ++j) ks[j] = ks[j + 1];
            ks[LDEPTH - 1] = 0ULL;
        }
    }

    // ---- phase C: candidate dict rows -> smem ----
#pragma unroll
    for (int j = 0; j < NCAND; ++j) {
        const float* dr = dict + (size_t)cand[j] * DIM;
#pragma unroll
        for (int q4 = 0; q4 < 4; ++q4)
            drows[j * DSTR + q4 * 32 + l] = dr[q4 * 32 + l];
    }
    __syncwarp();

    // ---- exact x norm (fp64 accumulate) ----
    double s = 0.0;
#pragma unroll
    for (int q4 = 0; q4 < 4; ++q4) {
        double xv = (double)xrow[q4 * 32 + l];
        s += xv * xv;
    }
#pragma unroll
    for (int o = 16; o; o >>= 1) s += __shfl_xor_sync(0xffffffffu, s, o);
    float xn = fmaxf(sqrtf((float)s), COS_EPS);

    // ---- phase D: exact fp32 serial-FMA dot + IEEE divide ----
    uint64_t qkey = 0ULL;
    if (l < NCAND) {
        float p = 0.0f;
        const float* dsm = drows + l * DSTR;
#pragma unroll
        for (int k = 0; k < DIM; ++k)
            p = fmaf(xrow[k], dsm[k], p);
        int qi = cand[l];
        float q = __fdiv_rn(p, __fmul_rn(xn, g_dn[qi]));
        qkey = packkey(q, ((uint32_t)(511 - qi) << 4) | (uint32_t)l);
    }

    // ---- phase E: exact top-8 (value desc, index asc) ----
    float tv[8]; int ti[8]; int ts[8];
#pragma unroll
    for (int r = 0; r < 8; ++r) {
        uint64_t m = warpmax64(qkey);
        tv[r] = unpackval(m);
        ti[r] = 511 - (int)(((uint32_t)m >> 4) & 0x1FFu);
        ts[r] = (int)((uint32_t)m & 0xFu);
        if (qkey == m) qkey = 0ULL;
    }

    // ---- softmaxes ----
    float mx = tv[0];
    float e[8], e2[8], se = 0.f, se2 = 0.f;
#pragma unroll
    for (int k = 0; k < 8; ++k) {
        e[k] = expf(tv[k] - mx);            se += e[k];
        e2[k] = expf(20.0f * (tv[k] - mx)); se2 += e2[k];
    }
    float wgt[8], ew[8];
#pragma unroll
    for (int k = 0; k < 8; ++k) { wgt[k] = e[k] / se; ew[k] = e2[k] / se2; }

    // ---- group_emb from smem candidate rows ----
    float4 xv = *(const float4*)(xrow + l * 4);
    float4 g = make_float4(0.f, 0.f, 0.f, 0.f);
#pragma unroll
    for (int k = 0; k < 8; ++k) {
        float4 dv = *(const float4*)(drows + ts[k] * DSTR + l * 4);
        g.x += wgt[k] * dv.x; g.y += wgt[k] * dv.y;
        g.z += wgt[k] * dv.z; g.w += wgt[k] * dv.w;
    }
    *(float4*)(ge + row * DIM + l * 4) = g;

    if (l == 0) {
        float4 u0 = make_float4((float)ti[0], (float)ti[1], (float)ti[2], (float)ti[3]);
        float4 u1 = make_float4((float)ti[4], (float)ti[5], (float)ti[6], (float)ti[7]);
        *(float4*)(idxo + row * TOPK) = u0;
        *(float4*)(idxo + row * TOPK + 4) = u1;
    }

    // ---- scatter-reduce EMA statistics ----
    const int p = (int)(blockIdx.x & (PPART - 1));
    if (l < 8) atomicAdd(g_csize + p * NCLUST + ti[l], ew[l]);
#pragma unroll
    for (int k = 0; k < 8; ++k) {
        float sc = ew[k];
        float* ptr = g_isum + ((size_t)p * NCLUST + (size_t)ti[k]) * DIM + l * 4;
        red4(ptr, sc * xv.x, sc * xv.y, sc * xv.z, sc * xv.w);
    }
}

// ---------------- kernel: finalize EMA dictionary ----------------
__global__ void finalize_kernel(const float* __restrict__ dict, float* __restrict__ ndict) {
    int c = blockIdx.x;
    int d = threadIdx.x;
    float cs = 0.f;
#pragma unroll 8
    for (int p = 0; p < PPART; ++p) cs += g_csize[p * NCLUST + c];
    float s = 0.f;
#pragma unroll 8
    for (int p = 0; p < PPART; ++p) s += g_isum[((size_t)p * NCLUST + c) * DIM + d];
    float dv = dict[c * DIM + d];
    float nv = (cs != 0.0f) ? (dv * 0.1f + (s / cs) * 0.9f) : dv;
    ndict[c * DIM + d] = nv;
}

// ---------------- launch ----------------
extern "C" void kernel_launch(void* const* d_in, const int* in_sizes, int n_in,
                              void* d_out, int out_size) {
    const float* x = (const float*)d_in[0];
    const float* dict = (const float*)d_in[1];
    const size_t N = (size_t)in_sizes[0] / DIM;

    float* out = (float*)d_out;
    float* ge    = out;
    float* idxo  = ge + N * DIM;
    float* dist  = idxo + N * TOPK;
    float* ndict = dist + N * NCLUST;

    void* pcs = nullptr; void* pis = nullptr;
    cudaGetSymbolAddress(&pcs, g_csize);
    cudaGetSymbolAddress(&pis, g_isum);
    cudaMemsetAsync(pcs, 0, sizeof(float) * PPART * NCLUST);
    cudaMemsetAsync(pis, 0, sizeof(float) * (size_t)PPART * NCLUST * DIM);

    xnorm_kernel<<<(unsigned)(N / 8), 256>>>(x);
    prep_norm<<<NCLUST, DIM>>>(dict);
    prep_split<<<NCLUST * DIM / 256, 256>>>(dict);

    const int smem = (2 * BM + 2 * BN) * SSTR * (int)sizeof(__nv_bfloat16);
    cudaFuncSetAttribute(gemm_bf16x3, cudaFuncAttributeMaxDynamicSharedMemorySize, smem);
    dim3 grid(NCLUST / BN, (unsigned)(N / BM));
    gemm_bf16x3<<<grid, 256, smem>>>(x, dist);

    topk_kernel<<<(unsigned)(N / 4), 128>>>(dist, x, dict, ge, idxo);

    finalize_kernel<<<NCLUST, DIM>>>(dict, ndict);
}

// round 5
// speedup vs baseline: 2.3973x; 1.4484x over previous
#include <cuda_runtime.h>
#include <cuda_bf16.h>
#include <cstdint>
#include <math.h>

#define DIM 128
#define NCLUST 512
#define TOPK 8
#define PPART 64
#define NMAX 262144
#define COS_EPS 1e-8f

#define BM 256
#define BN 128
#define SSTR 136   // smem row stride in bf16 halves (conflict-free for ldmatrix)

// ---------------- scratch ----------------
__device__ __nv_bfloat16 g_dhi[NCLUST * DIM];
__device__ __nv_bfloat16 g_dlo[NCLUST * DIM];
__device__ float g_dn[NCLUST];
__device__ float g_invdn[NCLUST];
__device__ float g_xinv[NMAX];
__device__ float g_csize[PPART * NCLUST];
__device__ float g_isum[(size_t)PPART * NCLUST * DIM];

// ---------------- kernel: x row inverse norms ----------------
__global__ __launch_bounds__(256)
void xnorm_kernel(const float* __restrict__ x) {
    const int l = threadIdx.x & 31;
    const int w = threadIdx.x >> 5;
    const size_t row = (size_t)blockIdx.x * 8 + w;
    float4 v = *(const float4*)(x + row * DIM + l * 4);
    float sq = v.x * v.x + v.y * v.y + v.z * v.z + v.w * v.w;
#pragma unroll
    for (int o = 16; o; o >>= 1) sq += __shfl_xor_sync(0xffffffffu, sq, o);
    if (l == 0) g_xinv[row] = 1.0f / fmaxf(sqrtf(sq), COS_EPS);
}

// ---------------- kernel: dict norms + hi/lo split (merged) ----------------
__global__ void prep_kernel(const float* __restrict__ dict) {
    int c = blockIdx.x;
    int d = threadIdx.x;
    __shared__ double red[DIM];
    float v = dict[c * DIM + d];
    red[d] = (double)v * (double)v;
    __syncthreads();
#pragma unroll
    for (int s = 64; s > 0; s >>= 1) {
        if (d < s) red[d] += red[d + s];
        __syncthreads();
    }
    __nv_bfloat16 hi = __float2bfloat16(v);
    g_dhi[c * DIM + d] = hi;
    g_dlo[c * DIM + d] = __float2bfloat16(v - __bfloat162float(hi));
    if (d == 0) {
        float dn = fmaxf(sqrtf((float)red[0]), COS_EPS);
        g_dn[c] = dn;
        g_invdn[c] = 1.0f / dn;
    }
}

// ---------------- mma / ldmatrix helpers ----------------
__device__ __forceinline__ void mma16816(float* d, uint32_t a0, uint32_t a1, uint32_t a2, uint32_t a3,
                                         uint32_t b0, uint32_t b1) {
    asm volatile("mma.sync.aligned.m16n8k16.row.col.f32.bf16.bf16.f32 "
                 "{%0,%1,%2,%3},{%4,%5,%6,%7},{%8,%9},{%0,%1,%2,%3};"
                 : "+f"(d[0]), "+f"(d[1]), "+f"(d[2]), "+f"(d[3])
                 : "r"(a0), "r"(a1), "r"(a2), "r"(a3), "r"(b0), "r"(b1));
}
__device__ __forceinline__ void ldmx4(uint32_t* r, const __nv_bfloat16* p) {
    uint32_t a = (uint32_t)__cvta_generic_to_shared(p);
    asm volatile("ldmatrix.sync.aligned.m8n8.x4.shared.b16 {%0,%1,%2,%3}, [%4];"
                 : "=r"(r[0]), "=r"(r[1]), "=r"(r[2]), "=r"(r[3]) : "r"(a));
}

// ---------------- kernel: distances GEMM (bf16x3 tensor cores) ----------------
__global__ __launch_bounds__(256, 1)
void gemm_bf16x3(const float* __restrict__ x, float* __restrict__ dist) {
    extern __shared__ __nv_bfloat16 smh[];
    __nv_bfloat16* Ahi = smh;
    __nv_bfloat16* Alo = Ahi + BM * SSTR;
    __nv_bfloat16* Bhi = Alo + BM * SSTR;
    __nv_bfloat16* Blo = Bhi + BN * SSTR;
    __shared__ float srinv[BM];
    __shared__ float ssinv[BN];

    const int t = threadIdx.x;
    const int l = t & 31;
    const int wid = t >> 5;
    const int rowBase = blockIdx.y * BM;
    const int colBase = blockIdx.x * BN;

    if (t < BN) ssinv[t] = g_invdn[colBase + t];
    srinv[t] = g_xinv[rowBase + t];

    const float4* xb = (const float4*)(x + (size_t)rowBase * DIM);
#pragma unroll
    for (int i = 0; i < 32; ++i) {
        int flat = i * 256 + t;
        int r = flat >> 5, c4 = flat & 31;
        float4 v = xb[flat];
        __nv_bfloat162 h01 = __floats2bfloat162_rn(v.x, v.y);
        __nv_bfloat162 h23 = __floats2bfloat162_rn(v.z, v.w);
        __nv_bfloat162 l01 = __floats2bfloat162_rn(v.x - __bfloat162float(h01.x),
                                                   v.y - __bfloat162float(h01.y));
        __nv_bfloat162 l23 = __floats2bfloat162_rn(v.z - __bfloat162float(h23.x),
                                                   v.w - __bfloat162float(h23.y));
        __nv_bfloat16* ah = Ahi + r * SSTR + c4 * 4;
        __nv_bfloat16* al = Alo + r * SSTR + c4 * 4;
        *(__nv_bfloat162*)(ah) = h01;
        *(__nv_bfloat162*)(ah + 2) = h23;
        *(__nv_bfloat162*)(al) = l01;
        *(__nv_bfloat162*)(al + 2) = l23;
    }
    {
        const uint4* bh = (const uint4*)(g_dhi + (size_t)colBase * DIM);
        const uint4* bl = (const uint4*)(g_dlo + (size_t)colBase * DIM);
#pragma unroll
        for (int i = 0; i < 8; ++i) {
            int flat = i * 256 + t;
            int r = flat >> 4, h8 = flat & 15;
            *(uint4*)(Bhi + r * SSTR + h8 * 8) = bh[flat];
            *(uint4*)(Blo + r * SSTR + h8 * 8) = bl[flat];
        }
    }
    __syncthreads();

    const int wm = (wid >> 1) * 64;
    const int wn = (wid & 1) * 64;
    const int g = l >> 2;
    const int tg = l & 3;
    const int lrow = l & 15;
    const int lk8 = l >> 4;

    float acc[4][8][4];
#pragma unroll
    for (int m = 0; m < 4; ++m)
#pragma unroll
        for (int n = 0; n < 8; ++n)
#pragma unroll
            for (int j = 0; j < 4; ++j) acc[m][n][j] = 0.0f;

#pragma unroll
    for (int ks = 0; ks < 8; ++ks) {
        const int k = ks * 16;
        uint32_t ah[4][4], al[4][4];
#pragma unroll
        for (int m = 0; m < 4; ++m) {
            int off = (wm + m * 16 + lrow) * SSTR + k + lk8 * 8;
            ldmx4(ah[m], Ahi + off);
            ldmx4(al[m], Alo + off);
        }
#pragma unroll
        for (int nt = 0; nt < 4; ++nt) {
            uint32_t bh[4], bl[4];
            int off = (wn + nt * 16 + lrow) * SSTR + k + lk8 * 8;
            ldmx4(bh, Bhi + off);
            ldmx4(bl, Blo + off);
#pragma unroll
            for (int m = 0; m < 4; ++m) {
#pragma unroll
                for (int s = 0; s < 2; ++s) {
                    int n = nt * 2 + s;
                    mma16816(acc[m][n], ah[m][0], ah[m][1], ah[m][2], ah[m][3], bh[s], bh[s + 2]);
                    mma16816(acc[m][n], ah[m][0], ah[m][1], ah[m][2], ah[m][3], bl[s], bl[s + 2]);
                    mma16816(acc[m][n], al[m][0], al[m][1], al[m][2], al[m][3], bh[s], bh[s + 2]);
                }
            }
        }
    }

#pragma unroll
    for (int m = 0; m < 4; ++m) {
#pragma unroll
        for (int n = 0; n < 8; ++n) {
            int r0 = wm + m * 16 + g;
            int c0 = wn + n * 8 + 2 * tg;
            float ri0 = srinv[r0], ri1 = srinv[r0 + 8];
            float s0 = ssinv[c0], s1 = ssinv[c0 + 1];
            size_t base0 = (size_t)(rowBase + r0) * NCLUST + colBase + c0;
            float2 o0 = make_float2(acc[m][n][0] * ri0 * s0, acc[m][n][1] * ri0 * s1);
            float2 o1 = make_float2(acc[m][n][2] * ri1 * s0, acc[m][n][3] * ri1 * s1);
            *(float2*)(dist + base0) = o0;
            *(float2*)(dist + base0 + 8 * NCLUST) = o1;
        }
    }
}

// ---------------- topk helpers ----------------
__device__ __forceinline__ uint64_t packkey(float v, uint32_t low) {
    uint32_t u = __float_as_uint(v);
    u ^= ((uint32_t)((int)u >> 31)) | 0x80000000u;
    return ((uint64_t)u << 32) | low;
}
__device__ __forceinline__ float unpackval(uint64_t k) {
    uint32_t o = (uint32_t)(k >> 32);
    uint32_t u = (o & 0x80000000u) ? (o & 0x7FFFFFFFu) : ~o;
    return __uint_as_float(u);
}
__device__ __forceinline__ uint64_t warpmax64(uint64_t v) {
#pragma unroll
    for (int o = 16; o; o >>= 1) {
        uint64_t ov = __shfl_xor_sync(0xffffffffu, v, o);
        if (ov > v) v = ov;
    }
    return v;
}
__device__ __forceinline__ void red4(float* ptr, float a, float b, float c, float d) {
    asm volatile("red.global.add.v4.f32 [%0], {%1,%2,%3,%4};"
                 :: "l"(ptr), "f"(a), "f"(b), "f"(c), "f"(d) : "memory");
}

// ---------------- kernel: threshold-select + exact re-rank + outputs ----------------
__global__ __launch_bounds__(256)
void topk_kernel(const float* __restrict__ dist, const float* __restrict__ x,
                 const float* __restrict__ dict, float* __restrict__ ge,
                 float* __restrict__ idxo) {
    __shared__ float sxrow[8][128];
    __shared__ int scand[8][32];
    const int t = threadIdx.x;
    const int l = t & 31;
    const int w = t >> 5;
    const size_t row = (size_t)blockIdx.x * 8 + w;
    float* xs = sxrow[w];

    // x row -> smem (also kept in xv for later)
    float4 xv = *(const float4*)(x + row * DIM + l * 4);
    *(float4*)(xs + l * 4) = xv;

    // dist row -> 16 regs
    const float* drow = dist + row * NCLUST;
    float4 vv[4];
#pragma unroll
    for (int c = 0; c < 4; ++c) vv[c] = *(const float4*)(drow + c * 128 + l * 4);

    // lane max (tree of 15)
    float lm;
    {
        float m0 = fmaxf(fmaxf(vv[0].x, vv[0].y), fmaxf(vv[0].z, vv[0].w));
        float m1 = fmaxf(fmaxf(vv[1].x, vv[1].y), fmaxf(vv[1].z, vv[1].w));
        float m2 = fmaxf(fmaxf(vv[2].x, vv[2].y), fmaxf(vv[2].z, vv[2].w));
        float m3 = fmaxf(fmaxf(vv[3].x, vv[3].y), fmaxf(vv[3].z, vv[3].w));
        lm = fmaxf(fmaxf(m0, m1), fmaxf(m2, m3));
    }

    // bitonic sort lane maxima ascending across lanes; tau = 12th largest (lane 20)
    float bv = lm;
#pragma unroll
    for (int k = 2; k <= 32; k <<= 1) {
#pragma unroll
        for (int j = k >> 1; j; j >>= 1) {
            float ov = __shfl_xor_sync(0xffffffffu, bv, j);
            bool dir = ((l & k) == 0);
            bool lower = ((l & j) == 0);
            bv = (dir == lower) ? fminf(bv, ov) : fmaxf(bv, ov);
        }
    }
    const float tau = __shfl_sync(0xffffffffu, bv, 20);

    // ballot-compaction of candidate indices (>= tau) into smem
    int nc = 0;
#pragma unroll
    for (int c = 0; c < 4; ++c) {
#pragma unroll
        for (int q = 0; q < 4; ++q) {
            float val = (q == 0) ? vv[c].x : (q == 1) ? vv[c].y : (q == 2) ? vv[c].z : vv[c].w;
            bool p = (val >= tau);
            unsigned mk = __ballot_sync(0xffffffffu, p);
            if (p) {
                int pos = nc + __popc(mk & ((1u << l) - 1u));
                if (pos < 32) scand[w][pos] = c * 128 + l * 4 + q;
            }
            nc += __popc(mk);
        }
    }
    if (nc > 32) nc = 32;
    __syncwarp();

    // exact x norm (fp64 accumulate, correctly rounded)
    double s = (double)xv.x * xv.x + (double)xv.y * xv.y +
               (double)xv.z * xv.z + (double)xv.w * xv.w;
#pragma unroll
    for (int o = 16; o; o >>= 1) s += __shfl_xor_sync(0xffffffffu, s, o);
    const float xn = fmaxf(sqrtf((float)s), COS_EPS);

    // exact fp32 serial-FMA dot + IEEE divide for each candidate (one per lane)
    uint64_t qkey = 0ULL;
    if (l < nc) {
        const int ci = scand[w][l];
        const float4* dr4 = (const float4*)(dict + (size_t)ci * DIM);
        float4 b0[8], b1[8];
#pragma unroll
        for (int j = 0; j < 8; ++j) b0[j] = dr4[j];
#pragma unroll
        for (int j = 0; j < 8; ++j) b1[j] = dr4[8 + j];
        float p = 0.0f;
#pragma unroll
        for (int j = 0; j < 8; ++j) {
            p = fmaf(xs[j * 4 + 0], b0[j].x, p);
            p = fmaf(xs[j * 4 + 1], b0[j].y, p);
            p = fmaf(xs[j * 4 + 2], b0[j].z, p);
            p = fmaf(xs[j * 4 + 3], b0[j].w, p);
        }
#pragma unroll
        for (int j = 0; j < 8; ++j) b0[j] = dr4[16 + j];
#pragma unroll
        for (int j = 0; j < 8; ++j) {
            p = fmaf(xs[32 + j * 4 + 0], b1[j].x, p);
            p = fmaf(xs[32 + j * 4 + 1], b1[j].y, p);
            p = fmaf(xs[32 + j * 4 + 2], b1[j].z, p);
            p = fmaf(xs[32 + j * 4 + 3], b1[j].w, p);
        }
#pragma unroll
        for (int j = 0; j < 8; ++j) b1[j] = dr4[24 + j];
#pragma unroll
        for (int j = 0; j < 8; ++j) {
            p = fmaf(xs[64 + j * 4 + 0], b0[j].x, p);
            p = fmaf(xs[64 + j * 4 + 1], b0[j].y, p);
            p = fmaf(xs[64 + j * 4 + 2], b0[j].z, p);
            p = fmaf(xs[64 + j * 4 + 3], b0[j].w, p);
        }
#pragma unroll
        for (int j = 0; j < 8; ++j) {
            p = fmaf(xs[96 + j * 4 + 0], b1[j].x, p);
            p = fmaf(xs[96 + j * 4 + 1], b1[j].y, p);
            p = fmaf(xs[96 + j * 4 + 2], b1[j].z, p);
            p = fmaf(xs[96 + j * 4 + 3], b1[j].w, p);
        }
        float q = __fdiv_rn(p, __fmul_rn(xn, g_dn[ci]));
        qkey = packkey(q, (uint32_t)(511 - ci));
    }

    // exact top-8 (value desc, index asc)
    float tv[8]; int ti[8];
#pragma unroll
    for (int r = 0; r < 8; ++r) {
        uint64_t mm = warpmax64(qkey);
        tv[r] = unpackval(mm);
        ti[r] = 511 - (int)((uint32_t)mm & 0x1FFu);
        if (qkey == mm) qkey = 0ULL;
    }

    // softmaxes (fast exp; weights are continuous, not tie-sensitive)
    const float mx = tv[0];
    float e[8], e2[8], se = 0.f, se2 = 0.f;
#pragma unroll
    for (int k = 0; k < 8; ++k) {
        e[k] = __expf(tv[k] - mx);            se += e[k];
        e2[k] = __expf(20.0f * (tv[k] - mx)); se2 += e2[k];
    }
    float wgt[8], ew[8];
#pragma unroll
    for (int k = 0; k < 8; ++k) { wgt[k] = e[k] / se; ew[k] = e2[k] / se2; }

    // group_emb (dict rows are L2-hot)
    float4 g = make_float4(0.f, 0.f, 0.f, 0.f);
#pragma unroll
    for (int k = 0; k < 8; ++k) {
        float4 dv = *(const float4*)(dict + (size_t)ti[k] * DIM + l * 4);
        g.x += wgt[k] * dv.x; g.y += wgt[k] * dv.y;
        g.z += wgt[k] * dv.z; g.w += wgt[k] * dv.w;
    }
    *(float4*)(ge + row * DIM + l * 4) = g;

    if (l == 0) {
        float4 u0 = make_float4((float)ti[0], (float)ti[1], (float)ti[2], (float)ti[3]);
        float4 u1 = make_float4((float)ti[4], (float)ti[5], (float)ti[6], (float)ti[7]);
        *(float4*)(idxo + row * TOPK) = u0;
        *(float4*)(idxo + row * TOPK + 4) = u1;
    }

    // scatter-reduce EMA statistics
    const int pp = (int)(blockIdx.x & (PPART - 1));
    if (l < 8) atomicAdd(g_csize + pp * NCLUST + ti[l], ew[l]);
#pragma unroll
    for (int k = 0; k < 8; ++k) {
        float sc = ew[k];
        float* ptr = g_isum + ((size_t)pp * NCLUST + (size_t)ti[k]) * DIM + l * 4;
        red4(ptr, sc * xv.x, sc * xv.y, sc * xv.z, sc * xv.w);
    }
}

// ---------------- kernel: finalize EMA dictionary ----------------
__global__ void finalize_kernel(const float* __restrict__ dict, float* __restrict__ ndict) {
    int c = blockIdx.x;
    int d = threadIdx.x;
    float cs = 0.f;
#pragma unroll 8
    for (int p = 0; p < PPART; ++p) cs += g_csize[p * NCLUST + c];
    float s = 0.f;
#pragma unroll 8
    for (int p = 0; p < PPART; ++p) s += g_isum[((size_t)p * NCLUST + c) * DIM + d];
    float dv = dict[c * DIM + d];
    float nv = (cs != 0.0f) ? (dv * 0.1f + (s / cs) * 0.9f) : dv;
    ndict[c * DIM + d] = nv;
}

// ---------------- launch ----------------
extern "C" void kernel_launch(void* const* d_in, const int* in_sizes, int n_in,
                              void* d_out, int out_size) {
    const float* x = (const float*)d_in[0];
    const float* dict = (const float*)d_in[1];
    const size_t N = (size_t)in_sizes[0] / DIM;

    float* out = (float*)d_out;
    float* ge    = out;
    float* idxo  = ge + N * DIM;
    float* dist  = idxo + N * TOPK;
    float* ndict = dist + N * NCLUST;

    void* pcs = nullptr; void* pis = nullptr;
    cudaGetSymbolAddress(&pcs, g_csize);
    cudaGetSymbolAddress(&pis, g_isum);
    cudaMemsetAsync(pcs, 0, sizeof(float) * PPART * NCLUST);
    cudaMemsetAsync(pis, 0, sizeof(float) * (size_t)PPART * NCLUST * DIM);

    xnorm_kernel<<<(unsigned)(N / 8), 256>>>(x);
    prep_kernel<<<NCLUST, DIM>>>(dict);

    const int smem = (2 * BM + 2 * BN) * SSTR * (int)sizeof(__nv_bfloat16);
    cudaFuncSetAttribute(gemm_bf16x3, cudaFuncAttributeMaxDynamicSharedMemorySize, smem);
    dim3 grid(NCLUST / BN, (unsigned)(N / BM));
    gemm_bf16x3<<<grid, 256, smem>>>(x, dist);

    topk_kernel<<<(unsigned)(N / 8), 256>>>(dist, x, dict, ge, idxo);

    finalize_kernel<<<NCLUST, DIM>>>(dict, ndict);
}